// round 1
// baseline (speedup 1.0000x reference)
#include <cuda_runtime.h>
#include <math.h>

// Problem constants
#define NB 64
#define NC 512
#define NM 1024
#define NKW 5
#define NKTOT 2048   // two K=1024 segments: hs | hb

// Scratch (device globals: no allocation allowed)
__device__ float g_pe[NC * NM];     // positional embedding [C, M]  (2 MB)
__device__ float g_y[NB * NC];      // mean_m x
__device__ float g_nu[NB * NC];     // mean_m h_in
__device__ float g_gate[NB * NC];   // sigmoid gate
__device__ float g_mu[NB * NC];     // gate * y  = mean_m hs

// Upper-triangular 128x128 tile pairs of the 512x512 output (4x4 tiles)
__constant__ int2 c_tp[10] = {{0,0},{0,1},{0,2},{0,3},{1,1},{1,2},{1,3},{2,2},{2,3},{3,3}};

// ---------------------------------------------------------------------------
// K0: positional embedding  pe[c,m] = (c even) ? sin(m*div) : cos(m*div)
//     div = exp(-(2*(c/2)) * ln(10000)/C)
// ---------------------------------------------------------------------------
__global__ void pe_kernel() {
    int c = blockIdx.x;
    int i = c >> 1;
    float dv = expf(-(float)(2 * i) * (logf(10000.0f) / (float)NC));
    bool is_sin = (c & 1) == 0;
    for (int m = threadIdx.x; m < NM; m += blockDim.x) {
        float ang = (float)m * dv;
        g_pe[c * NM + m] = is_sin ? sinf(ang) : cosf(ang);
    }
}

// ---------------------------------------------------------------------------
// K1: per-(b,c) sums: y = mean_m (h + pe), nu = mean_m h.   1 warp per row.
// ---------------------------------------------------------------------------
__global__ void stats_kernel(const float* __restrict__ h) {
    int warp = (blockIdx.x * blockDim.x + threadIdx.x) >> 5;
    int lane = threadIdx.x & 31;
    if (warp >= NB * NC) return;
    int c = warp % NC;
    const float4* h4 = (const float4*)(h + (size_t)warp * NM);
    const float4* p4 = (const float4*)(g_pe + (size_t)c * NM);
    float sh = 0.f, sp = 0.f;
    for (int i = lane; i < NM / 4; i += 32) {
        float4 hv = h4[i];
        float4 pv = p4[i];
        sh += (hv.x + hv.y) + (hv.z + hv.w);
        sp += (pv.x + pv.y) + (pv.z + pv.w);
    }
    float sx = sh + sp;
    #pragma unroll
    for (int o = 16; o; o >>= 1) {
        sx += __shfl_xor_sync(0xffffffffu, sx, o);
        sh += __shfl_xor_sync(0xffffffffu, sh, o);
    }
    if (lane == 0) {
        g_y[warp]  = sx * (1.0f / NM);
        g_nu[warp] = sh * (1.0f / NM);
    }
}

// ---------------------------------------------------------------------------
// K2: gate[b,c] = sigmoid(sum_k y_pad[b,c+k-2]*w[c,k] + bias[c]);  mu = gate*y
// ---------------------------------------------------------------------------
__global__ void gate_kernel(const float* __restrict__ w, const float* __restrict__ bias) {
    int idx = blockIdx.x * blockDim.x + threadIdx.x;
    if (idx >= NB * NC) return;
    int b = idx / NC, c = idx % NC;
    float acc = bias[c];
    #pragma unroll
    for (int k = 0; k < NKW; k++) {
        int cc = c + k - 2;
        float yv = (cc >= 0 && cc < NC) ? g_y[b * NC + cc] : 0.0f;
        acc = fmaf(yv, w[c * NKW + k], acc);
    }
    float gate = 1.0f / (1.0f + expf(-acc));
    g_gate[idx] = gate;
    g_mu[idx]   = gate * g_y[idx];
}

// ---------------------------------------------------------------------------
// K3: batched SYRK.  G[b][c][k] = k<M ? (h+pe)*gate : h  (K = 2048).
//     cov = acc/M - mu*mu' - nu*nu' + eps*I.  Symmetric: 10 tile pairs.
// ---------------------------------------------------------------------------
__device__ __forceinline__ float4 fetch4(const float* __restrict__ hb,
                                         const float* __restrict__ gate,
                                         int c, int k) {
    if (k < NM) {
        float4 hv = *(const float4*)(hb + (size_t)c * NM + k);
        float4 pv = *(const float4*)(g_pe + (size_t)c * NM + k);
        float g = gate[c];
        return make_float4((hv.x + pv.x) * g, (hv.y + pv.y) * g,
                           (hv.z + pv.z) * g, (hv.w + pv.w) * g);
    } else {
        return *(const float4*)(hb + (size_t)c * NM + (k - NM));
    }
}

__global__ __launch_bounds__(256, 2) void syrk_kernel(const float* __restrict__ h,
                                                      float* __restrict__ out) {
    __shared__ float As[16][128];
    __shared__ float Bs[16][128];

    int b = blockIdx.y;
    int2 tp = c_tp[blockIdx.x];
    int row0 = tp.x * 128;
    int col0 = tp.y * 128;
    const float* hb   = h + (size_t)b * NC * NM;
    const float* gate = g_gate + b * NC;

    int tid  = threadIdx.x;
    int lkk  = (tid & 3) << 2;   // k-offset within 16 (float4 granularity)
    int lrow = tid >> 2;         // 0..63 ; two passes cover 128 rows
    int tx = tid & 15, ty = tid >> 4;

    float acc[8][8];
    #pragma unroll
    for (int i = 0; i < 8; i++)
        #pragma unroll
        for (int j = 0; j < 8; j++) acc[i][j] = 0.0f;

    for (int k0 = 0; k0 < NKTOT; k0 += 16) {
        #pragma unroll
        for (int jj = 0; jj < 2; jj++) {
            int r = lrow + 64 * jj;
            float4 va = fetch4(hb, gate, row0 + r, k0 + lkk);
            As[lkk + 0][r] = va.x; As[lkk + 1][r] = va.y;
            As[lkk + 2][r] = va.z; As[lkk + 3][r] = va.w;
            float4 vb = fetch4(hb, gate, col0 + r, k0 + lkk);
            Bs[lkk + 0][r] = vb.x; Bs[lkk + 1][r] = vb.y;
            Bs[lkk + 2][r] = vb.z; Bs[lkk + 3][r] = vb.w;
        }
        __syncthreads();

        #pragma unroll
        for (int kk = 0; kk < 16; kk++) {
            float4 a0 = *(const float4*)&As[kk][ty * 8];
            float4 a1 = *(const float4*)&As[kk][ty * 8 + 4];
            float4 b0 = *(const float4*)&Bs[kk][tx * 8];
            float4 b1 = *(const float4*)&Bs[kk][tx * 8 + 4];
            float a[8] = {a0.x, a0.y, a0.z, a0.w, a1.x, a1.y, a1.z, a1.w};
            float bb[8] = {b0.x, b0.y, b0.z, b0.w, b1.x, b1.y, b1.z, b1.w};
            #pragma unroll
            for (int i = 0; i < 8; i++)
                #pragma unroll
                for (int j = 0; j < 8; j++)
                    acc[i][j] = fmaf(a[i], bb[j], acc[i][j]);
        }
        __syncthreads();
    }

    // Epilogue: cov = acc/M - mu_c*mu_d - nu_c*nu_d (+1e-8 on diag); write both halves
    const float* mu = g_mu + b * NC;
    const float* nu = g_nu + b * NC;
    float* outb = out + (size_t)b * NC * NC;
    const float invM = 1.0f / (float)NM;

    #pragma unroll
    for (int i = 0; i < 8; i++) {
        int cI = row0 + ty * 8 + i;
        float mc = mu[cI], nc = nu[cI];
        #pragma unroll
        for (int j = 0; j < 8; j++) {
            int dJ = col0 + tx * 8 + j;
            float v = acc[i][j] * invM - mc * mu[dJ] - nc * nu[dJ];
            if (cI == dJ) v += 1e-8f;
            outb[(size_t)cI * NC + dJ] = v;
            outb[(size_t)dJ * NC + cI] = v;
        }
    }
}

// ---------------------------------------------------------------------------
extern "C" void kernel_launch(void* const* d_in, const int* in_sizes, int n_in,
                              void* d_out, int out_size) {
    const float* h    = (const float*)d_in[0];   // [64,512,1,1024]
    const float* w    = (const float*)d_in[1];   // [512,5]
    const float* bias = (const float*)d_in[2];   // [512]
    float* out = (float*)d_out;                  // [64,512,512]

    pe_kernel<<<NC, 256>>>();
    stats_kernel<<<(NB * NC) / 8, 256>>>(h);     // 8 warps/block, 1 warp/row
    gate_kernel<<<(NB * NC + 255) / 256, 256>>>(w, bias);
    dim3 grid(10, NB);
    syrk_kernel<<<grid, 256>>>(h, out);
}

// round 4
// speedup vs baseline: 1.9818x; 1.9818x over previous
#include <cuda_runtime.h>
#include <cuda_bf16.h>
#include <math.h>
#include <stdint.h>

#define NB 64
#define NC 512
#define NM 1024
#define NKW 5
#define BK 32          // fp32 k per chunk
#define LDT 40         // padded bf16 tile row stride (elements) -> 80B rows

// Scratch
__device__ float g_pe[NC * NM];
__device__ float g_y[NB * NC];
__device__ float g_nu[NB * NC];
__device__ float g_gate[NB * NC];
__device__ float g_mu[NB * NC];

__constant__ int2 c_tp[10] = {{0,0},{0,1},{0,2},{0,3},{1,1},{1,2},{1,3},{2,2},{2,3},{3,3}};

// ---------------------------------------------------------------------------
__global__ void pe_kernel() {
    int c = blockIdx.x;
    int i = c >> 1;
    float dv = expf(-(float)(2 * i) * (logf(10000.0f) / (float)NC));
    bool is_sin = (c & 1) == 0;
    for (int m = threadIdx.x; m < NM; m += blockDim.x) {
        float ang = (float)m * dv;
        g_pe[c * NM + m] = is_sin ? sinf(ang) : cosf(ang);
    }
}

__global__ void stats_kernel(const float* __restrict__ h) {
    int warp = (blockIdx.x * blockDim.x + threadIdx.x) >> 5;
    int lane = threadIdx.x & 31;
    if (warp >= NB * NC) return;
    int c = warp % NC;
    const float4* h4 = (const float4*)(h + (size_t)warp * NM);
    const float4* p4 = (const float4*)(g_pe + (size_t)c * NM);
    float sh = 0.f, sp = 0.f;
    for (int i = lane; i < NM / 4; i += 32) {
        float4 hv = h4[i];
        float4 pv = p4[i];
        sh += (hv.x + hv.y) + (hv.z + hv.w);
        sp += (pv.x + pv.y) + (pv.z + pv.w);
    }
    float sx = sh + sp;
    #pragma unroll
    for (int o = 16; o; o >>= 1) {
        sx += __shfl_xor_sync(0xffffffffu, sx, o);
        sh += __shfl_xor_sync(0xffffffffu, sh, o);
    }
    if (lane == 0) {
        g_y[warp]  = sx * (1.0f / NM);
        g_nu[warp] = sh * (1.0f / NM);
    }
}

__global__ void gate_kernel(const float* __restrict__ w, const float* __restrict__ bias) {
    int idx = blockIdx.x * blockDim.x + threadIdx.x;
    if (idx >= NB * NC) return;
    int b = idx / NC, c = idx % NC;
    float acc = bias[c];
    #pragma unroll
    for (int k = 0; k < NKW; k++) {
        int cc = c + k - 2;
        float yv = (cc >= 0 && cc < NC) ? g_y[b * NC + cc] : 0.0f;
        acc = fmaf(yv, w[c * NKW + k], acc);
    }
    float gate = 1.0f / (1.0f + expf(-acc));
    g_gate[idx] = gate;
    g_mu[idx]   = gate * g_y[idx];
}

// ---------------------------------------------------------------------------
// HMMA SYRK: cov = (Hs I_hat Hs' + Hb I_hat Hb') + eps*I, via bf16 hi/lo split
// ---------------------------------------------------------------------------
__device__ __forceinline__ uint32_t smem_u32(const void* p) {
    uint32_t a;
    asm("{ .reg .u64 t; cvta.to.shared.u64 t, %1; cvt.u32.u64 %0, t; }" : "=r"(a) : "l"(p));
    return a;
}
__device__ __forceinline__ void ldsm_x4(uint32_t* r, uint32_t addr) {
    asm volatile("ldmatrix.sync.aligned.m8n8.x4.shared.b16 {%0,%1,%2,%3}, [%4];"
                 : "=r"(r[0]), "=r"(r[1]), "=r"(r[2]), "=r"(r[3]) : "r"(addr));
}
__device__ __forceinline__ void mma16816(float* d, const uint32_t* a, const uint32_t* b) {
    asm volatile(
        "mma.sync.aligned.m16n8k16.row.col.f32.bf16.bf16.f32 "
        "{%0,%1,%2,%3}, {%4,%5,%6,%7}, {%8,%9}, {%0,%1,%2,%3};"
        : "+f"(d[0]), "+f"(d[1]), "+f"(d[2]), "+f"(d[3])
        : "r"(a[0]), "r"(a[1]), "r"(a[2]), "r"(a[3]), "r"(b[0]), "r"(b[1]));
}
__device__ __forceinline__ uint32_t pack2(__nv_bfloat16 a, __nv_bfloat16 b) {
    return (uint32_t)__bfloat16_as_ushort(a) | ((uint32_t)__bfloat16_as_ushort(b) << 16);
}

__global__ __launch_bounds__(256, 2) void syrk_hmma(const float* __restrict__ h,
                                                    float* __restrict__ out) {
    __shared__ __align__(16) __nv_bfloat16 sAH[128 * LDT];
    __shared__ __align__(16) __nv_bfloat16 sAL[128 * LDT];
    __shared__ __align__(16) __nv_bfloat16 sBH[128 * LDT];
    __shared__ __align__(16) __nv_bfloat16 sBL[128 * LDT];

    int tid = threadIdx.x;
    int lane = tid & 31;
    int wid = tid >> 5;
    int b = blockIdx.y;
    int2 tp = c_tp[blockIdx.x];
    int row0 = tp.x * 128;
    int col0 = tp.y * 128;
    const float* hbp  = h + (size_t)b * NC * NM;
    const float* gate = g_gate + b * NC;

    // warp tile: 64 x 32
    int wm = (wid >> 2) * 64;
    int wn = (wid & 3) * 32;

    float acc[4][4][4];
    #pragma unroll
    for (int i = 0; i < 4; i++)
        #pragma unroll
        for (int j = 0; j < 4; j++)
            #pragma unroll
            for (int q = 0; q < 4; q++) acc[i][j][q] = 0.0f;

    uint32_t uAH = smem_u32(sAH), uAL = smem_u32(sAL);
    uint32_t uBH = smem_u32(sBH), uBL = smem_u32(sBL);

    // precomputed ldmatrix lane offsets (element units)
    int aRowOff = lane & 15;                                  // + wm + fm*16
    int aColOff = (lane >> 4) * 8;                            // + k0
    int bRowOff = (lane & 7) + ((lane >> 4) << 3);            // + wn / +16
    int bColOff = ((lane >> 3) & 1) * 8;                      // + k0

    for (int part = 0; part < 2; part++) {
        for (int kc = 0; kc < 32; kc++) {
            int kb = kc * BK;
            // ---- stage: build 4 bf16 tiles ----
            #pragma unroll
            for (int it = 0; it < 8; it++) {
                int item = it * 256 + tid;
                int op = item >> 10;            // 0=A rows, 1=B rows
                int r  = (item >> 3) & 127;
                int g  = item & 7;
                int c  = (op ? col0 : row0) + r;
                float4 hv = *(const float4*)(hbp + (size_t)c * NM + kb + g * 4);
                float v0, v1, v2, v3;
                if (part == 0) {
                    float4 pv = *(const float4*)(g_pe + (size_t)c * NM + kb + g * 4);
                    float gg = gate[c];
                    v0 = (hv.x + pv.x) * gg; v1 = (hv.y + pv.y) * gg;
                    v2 = (hv.z + pv.z) * gg; v3 = (hv.w + pv.w) * gg;
                } else {
                    v0 = hv.x; v1 = hv.y; v2 = hv.z; v3 = hv.w;
                }
                __nv_bfloat16 h0 = __float2bfloat16(v0), h1 = __float2bfloat16(v1);
                __nv_bfloat16 h2 = __float2bfloat16(v2), h3 = __float2bfloat16(v3);
                __nv_bfloat16 l0 = __float2bfloat16(v0 - __bfloat162float(h0));
                __nv_bfloat16 l1 = __float2bfloat16(v1 - __bfloat162float(h1));
                __nv_bfloat16 l2 = __float2bfloat16(v2 - __bfloat162float(h2));
                __nv_bfloat16 l3 = __float2bfloat16(v3 - __bfloat162float(h3));
                int eo = r * LDT + g * 4;
                __nv_bfloat16* tH = op ? sBH : sAH;
                __nv_bfloat16* tL = op ? sBL : sAL;
                *(uint2*)(tH + eo) = make_uint2(pack2(h0, h1), pack2(h2, h3));
                *(uint2*)(tL + eo) = make_uint2(pack2(l0, l1), pack2(l2, l3));
            }
            __syncthreads();

            // ---- MMA: 3 sections (HH, HL, LH), 2 k16-steps each ----
            #pragma unroll
            for (int sec = 0; sec < 3; sec++) {
                uint32_t aBase = (sec == 2) ? uAL : uAH;
                uint32_t bBase = (sec == 1) ? uBL : uBH;
                #pragma unroll
                for (int ks = 0; ks < 2; ks++) {
                    int k0 = ks * 16;
                    uint32_t af[4][4];
                    #pragma unroll
                    for (int fm = 0; fm < 4; fm++) {
                        uint32_t addr = aBase +
                            (uint32_t)(((wm + fm * 16 + aRowOff) * LDT + k0 + aColOff) * 2);
                        ldsm_x4(af[fm], addr);
                    }
                    uint32_t bf[4][2];
                    #pragma unroll
                    for (int half = 0; half < 2; half++) {
                        uint32_t r4[4];
                        uint32_t addr = bBase +
                            (uint32_t)(((wn + half * 16 + bRowOff) * LDT + k0 + bColOff) * 2);
                        ldsm_x4(r4, addr);
                        bf[half * 2 + 0][0] = r4[0]; bf[half * 2 + 0][1] = r4[1];
                        bf[half * 2 + 1][0] = r4[2]; bf[half * 2 + 1][1] = r4[3];
                    }
                    #pragma unroll
                    for (int fm = 0; fm < 4; fm++)
                        #pragma unroll
                        for (int fn = 0; fn < 4; fn++)
                            mma16816(acc[fm][fn], af[fm], bf[fn]);
                }
            }
            __syncthreads();
        }
    }

    // ---- epilogue ----
    const float* mug = g_mu + b * NC;
    const float* nug = g_nu + b * NC;
    float* outb = out + (size_t)b * NC * NC;
    const float invM = 1.0f / (float)NM;

    // per-thread rows: fm*16 + (lane>>2) and +8 ; cols: fn*8 + (lane&3)*2 and +1
    float muR[8], nuR[8], muC[8], nuC[8];
    #pragma unroll
    for (int fm = 0; fm < 4; fm++) {
        int r = row0 + wm + fm * 16 + (lane >> 2);
        muR[fm * 2]     = mug[r];     nuR[fm * 2]     = nug[r];
        muR[fm * 2 + 1] = mug[r + 8]; nuR[fm * 2 + 1] = nug[r + 8];
    }
    #pragma unroll
    for (int fn = 0; fn < 4; fn++) {
        int c = col0 + wn + fn * 8 + (lane & 3) * 2;
        muC[fn * 2]     = mug[c];     nuC[fn * 2]     = nug[c];
        muC[fn * 2 + 1] = mug[c + 1]; nuC[fn * 2 + 1] = nug[c + 1];
    }

    #pragma unroll
    for (int fm = 0; fm < 4; fm++) {
        #pragma unroll
        for (int fn = 0; fn < 4; fn++) {
            #pragma unroll
            for (int q = 0; q < 4; q++) {
                int rr = fm * 2 + (q >> 1);          // row half select (d2,d3 -> +8)
                int cc = fn * 2 + (q & 1);
                int rI = row0 + wm + fm * 16 + (lane >> 2) + (q >> 1) * 8;
                int cJ = col0 + wn + fn * 8 + (lane & 3) * 2 + (q & 1);
                float v = acc[fm][fn][q] * invM - muR[rr] * muC[cc] - nuR[rr] * nuC[cc];
                if (rI == cJ) v += 1e-8f;
                outb[(size_t)rI * NC + cJ] = v;
                outb[(size_t)cJ * NC + rI] = v;
            }
        }
    }
}

// ---------------------------------------------------------------------------
extern "C" void kernel_launch(void* const* d_in, const int* in_sizes, int n_in,
                              void* d_out, int out_size) {
    const float* h    = (const float*)d_in[0];
    const float* w    = (const float*)d_in[1];
    const float* bias = (const float*)d_in[2];
    float* out = (float*)d_out;

    pe_kernel<<<NC, 256>>>();
    stats_kernel<<<(NB * NC) / 8, 256>>>(h);
    gate_kernel<<<(NB * NC + 255) / 256, 256>>>(w, bias);
    dim3 grid(10, NB);
    syrk_hmma<<<grid, 256>>>(h, out);
}

// round 5
// speedup vs baseline: 2.7067x; 1.3658x over previous
#include <cuda_runtime.h>
#include <cuda_bf16.h>
#include <math.h>
#include <stdint.h>

#define NB 64
#define NC 512
#define NM 1024
#define NKW 5
#define LDT 40              // padded bf16 row stride (elements) -> 80B rows
#define TILE_BYTES (128 * LDT * 2)      // 10240
#define STAGE_BYTES (4 * TILE_BYTES)    // 40960
#define SMEM_TOTAL (2 * STAGE_BYTES)    // 81920

// Scratch
__device__ float g_pe[NC * NM];
__device__ float g_y[NB * NC];
__device__ float g_nu[NB * NC];
__device__ float g_gate[NB * NC];
__device__ float g_mu[NB * NC];
// bf16 hi/lo planes (64MB each)
__device__ __align__(16) __nv_bfloat16 g_hs_hi[NB * NC * NM];
__device__ __align__(16) __nv_bfloat16 g_hs_lo[NB * NC * NM];
__device__ __align__(16) __nv_bfloat16 g_hb_hi[NB * NC * NM];
__device__ __align__(16) __nv_bfloat16 g_hb_lo[NB * NC * NM];

__constant__ int2 c_tp[10] = {{0,0},{0,1},{0,2},{0,3},{1,1},{1,2},{1,3},{2,2},{2,3},{3,3}};

// ---------------------------------------------------------------------------
__global__ void pe_kernel() {
    int c = blockIdx.x;
    int i = c >> 1;
    float dv = expf(-(float)(2 * i) * (logf(10000.0f) / (float)NC));
    bool is_sin = (c & 1) == 0;
    for (int m = threadIdx.x; m < NM; m += blockDim.x) {
        float ang = (float)m * dv;
        g_pe[c * NM + m] = is_sin ? sinf(ang) : cosf(ang);
    }
}

__global__ void stats_kernel(const float* __restrict__ h) {
    int warp = (blockIdx.x * blockDim.x + threadIdx.x) >> 5;
    int lane = threadIdx.x & 31;
    if (warp >= NB * NC) return;
    int c = warp % NC;
    const float4* h4 = (const float4*)(h + (size_t)warp * NM);
    const float4* p4 = (const float4*)(g_pe + (size_t)c * NM);
    float sh = 0.f, sp = 0.f;
    for (int i = lane; i < NM / 4; i += 32) {
        float4 hv = h4[i];
        float4 pv = p4[i];
        sh += (hv.x + hv.y) + (hv.z + hv.w);
        sp += (pv.x + pv.y) + (pv.z + pv.w);
    }
    float sx = sh + sp;
    #pragma unroll
    for (int o = 16; o; o >>= 1) {
        sx += __shfl_xor_sync(0xffffffffu, sx, o);
        sh += __shfl_xor_sync(0xffffffffu, sh, o);
    }
    if (lane == 0) {
        g_y[warp]  = sx * (1.0f / NM);
        g_nu[warp] = sh * (1.0f / NM);
    }
}

__global__ void gate_kernel(const float* __restrict__ w, const float* __restrict__ bias) {
    int idx = blockIdx.x * blockDim.x + threadIdx.x;
    if (idx >= NB * NC) return;
    int b = idx / NC, c = idx % NC;
    float acc = bias[c];
    #pragma unroll
    for (int k = 0; k < NKW; k++) {
        int cc = c + k - 2;
        float yv = (cc >= 0 && cc < NC) ? g_y[b * NC + cc] : 0.0f;
        acc = fmaf(yv, w[c * NKW + k], acc);
    }
    float gate = 1.0f / (1.0f + expf(-acc));
    g_gate[idx] = gate;
    g_mu[idx]   = gate * g_y[idx];
}

// ---------------------------------------------------------------------------
// prep: split hs=(h+pe)*gate and hb=h into bf16 hi/lo planes. One block per row.
// ---------------------------------------------------------------------------
__device__ __forceinline__ uint32_t pack2(__nv_bfloat16 a, __nv_bfloat16 b) {
    return (uint32_t)__bfloat16_as_ushort(a) | ((uint32_t)__bfloat16_as_ushort(b) << 16);
}
__device__ __forceinline__ void split4(float v0, float v1, float v2, float v3,
                                       uint2* hi, uint2* lo) {
    __nv_bfloat16 h0 = __float2bfloat16(v0), h1 = __float2bfloat16(v1);
    __nv_bfloat16 h2 = __float2bfloat16(v2), h3 = __float2bfloat16(v3);
    __nv_bfloat16 l0 = __float2bfloat16(v0 - __bfloat162float(h0));
    __nv_bfloat16 l1 = __float2bfloat16(v1 - __bfloat162float(h1));
    __nv_bfloat16 l2 = __float2bfloat16(v2 - __bfloat162float(h2));
    __nv_bfloat16 l3 = __float2bfloat16(v3 - __bfloat162float(h3));
    *hi = make_uint2(pack2(h0, h1), pack2(h2, h3));
    *lo = make_uint2(pack2(l0, l1), pack2(l2, l3));
}

__global__ __launch_bounds__(256) void prep_kernel(const float* __restrict__ h) {
    int rowid = blockIdx.x;              // b*NC + c
    int c = rowid & (NC - 1);
    int t = threadIdx.x;                 // one float4 per thread
    size_t e = (size_t)rowid * NM + t * 4;
    float4 hv = *(const float4*)(h + e);
    float4 pv = *(const float4*)(g_pe + (size_t)c * NM + t * 4);
    float gg = g_gate[rowid];
    uint2 hi, lo;
    split4((hv.x + pv.x) * gg, (hv.y + pv.y) * gg,
           (hv.z + pv.z) * gg, (hv.w + pv.w) * gg, &hi, &lo);
    *(uint2*)(g_hs_hi + e) = hi;
    *(uint2*)(g_hs_lo + e) = lo;
    split4(hv.x, hv.y, hv.z, hv.w, &hi, &lo);
    *(uint2*)(g_hb_hi + e) = hi;
    *(uint2*)(g_hb_lo + e) = lo;
}

// ---------------------------------------------------------------------------
// SYRK on HMMA, pure bf16 GEMM with cp.async double buffering
// ---------------------------------------------------------------------------
__device__ __forceinline__ uint32_t smem_u32(const void* p) {
    uint32_t a;
    asm("{ .reg .u64 t; cvta.to.shared.u64 t, %1; cvt.u32.u64 %0, t; }" : "=r"(a) : "l"(p));
    return a;
}
__device__ __forceinline__ void ldsm_x4(uint32_t* r, uint32_t addr) {
    asm volatile("ldmatrix.sync.aligned.m8n8.x4.shared.b16 {%0,%1,%2,%3}, [%4];"
                 : "=r"(r[0]), "=r"(r[1]), "=r"(r[2]), "=r"(r[3]) : "r"(addr));
}
__device__ __forceinline__ void mma16816(float* d, const uint32_t* a, const uint32_t* b) {
    asm volatile(
        "mma.sync.aligned.m16n8k16.row.col.f32.bf16.bf16.f32 "
        "{%0,%1,%2,%3}, {%4,%5,%6,%7}, {%8,%9}, {%0,%1,%2,%3};"
        : "+f"(d[0]), "+f"(d[1]), "+f"(d[2]), "+f"(d[3])
        : "r"(a[0]), "r"(a[1]), "r"(a[2]), "r"(a[3]), "r"(b[0]), "r"(b[1]));
}
__device__ __forceinline__ void cp16(uint32_t dst, const void* src) {
    asm volatile("cp.async.cg.shared.global [%0], [%1], 16;" :: "r"(dst), "l"(src) : "memory");
}
__device__ __forceinline__ void cp_commit() {
    asm volatile("cp.async.commit_group;" ::: "memory");
}
template <int N>
__device__ __forceinline__ void cp_wait() {
    asm volatile("cp.async.wait_group %0;" :: "n"(N) : "memory");
}

extern __shared__ char dsm[];

__global__ __launch_bounds__(256, 2) void syrk_hmma2(float* __restrict__ out) {
    int tid = threadIdx.x;
    int lane = tid & 31;
    int wid = tid >> 5;
    int b = blockIdx.y;
    int2 tp = c_tp[blockIdx.x];
    int row0 = tp.x * 128;
    int col0 = tp.y * 128;

    uint32_t sb = smem_u32(dsm);

    // warp tile: 64 x 32
    int wm = (wid >> 2) * 64;
    int wn = (wid & 3) * 32;

    float acc[4][4][4];
    #pragma unroll
    for (int i = 0; i < 4; i++)
        #pragma unroll
        for (int j = 0; j < 4; j++)
            #pragma unroll
            for (int q = 0; q < 4; q++) acc[i][j][q] = 0.0f;

    // ldmatrix lane offsets (element units)
    int aRowOff = lane & 15;
    int aColOff = (lane >> 4) * 8;
    int bRowOff = (lane & 7) + ((lane >> 4) << 3);
    int bColOff = ((lane >> 3) & 1) * 8;

    // per-thread cp.async item decode (8 items/thread/stage)
    // item = it*256+tid: t=item>>9 (0:A_hi 1:A_lo 2:B_hi 3:B_lo), r=(item>>2)&127, ch=item&3
    const size_t rowbase = (size_t)b * NC;

    auto issue = [&](int s) {
        int part = s >> 5;               // 0 = hs, 1 = hb
        int k0 = (s & 31) * 32;
        uint32_t dstbase = sb + (uint32_t)(s & 1) * STAGE_BYTES;
        #pragma unroll
        for (int it = 0; it < 8; it++) {
            int item = it * 256 + tid;
            int t  = item >> 9;
            int r  = (item >> 2) & 127;
            int ch = item & 3;
            int row = ((t >= 2) ? col0 : row0) + r;
            const __nv_bfloat16* plane =
                part ? ((t & 1) ? g_hb_lo : g_hb_hi)
                     : ((t & 1) ? g_hs_lo : g_hs_hi);
            const void* src = plane + (rowbase + row) * NM + k0 + ch * 8;
            uint32_t dst = dstbase + (uint32_t)(t * TILE_BYTES + r * 80 + ch * 16);
            cp16(dst, src);
        }
        cp_commit();
    };

    issue(0);
    for (int s = 0; s < 64; s++) {
        if (s + 1 < 64) { issue(s + 1); cp_wait<1>(); }
        else            { cp_wait<0>(); }
        __syncthreads();

        uint32_t base = sb + (uint32_t)(s & 1) * STAGE_BYTES;
        uint32_t uAH = base;
        uint32_t uAL = base + TILE_BYTES;
        uint32_t uBH = base + 2 * TILE_BYTES;
        uint32_t uBL = base + 3 * TILE_BYTES;

        #pragma unroll
        for (int sec = 0; sec < 3; sec++) {
            uint32_t aBase = (sec == 2) ? uAL : uAH;
            uint32_t bBase = (sec == 1) ? uBL : uBH;
            #pragma unroll
            for (int ks = 0; ks < 2; ks++) {
                int k0 = ks * 16;
                uint32_t af[4][4];
                #pragma unroll
                for (int fm = 0; fm < 4; fm++) {
                    uint32_t addr = aBase +
                        (uint32_t)(((wm + fm * 16 + aRowOff) * LDT + k0 + aColOff) * 2);
                    ldsm_x4(af[fm], addr);
                }
                uint32_t bf[4][2];
                #pragma unroll
                for (int half = 0; half < 2; half++) {
                    uint32_t r4[4];
                    uint32_t addr = bBase +
                        (uint32_t)(((wn + half * 16 + bRowOff) * LDT + k0 + bColOff) * 2);
                    ldsm_x4(r4, addr);
                    bf[half * 2 + 0][0] = r4[0]; bf[half * 2 + 0][1] = r4[1];
                    bf[half * 2 + 1][0] = r4[2]; bf[half * 2 + 1][1] = r4[3];
                }
                #pragma unroll
                for (int fm = 0; fm < 4; fm++)
                    #pragma unroll
                    for (int fn = 0; fn < 4; fn++)
                        mma16816(acc[fm][fn], af[fm], bf[fn]);
            }
        }
        __syncthreads();
    }

    // ---- epilogue ----
    const float* mug = g_mu + b * NC;
    const float* nug = g_nu + b * NC;
    float* outb = out + (size_t)b * NC * NC;
    const float invM = 1.0f / (float)NM;

    float muR[8], nuR[8], muC[8], nuC[8];
    #pragma unroll
    for (int fm = 0; fm < 4; fm++) {
        int r = row0 + wm + fm * 16 + (lane >> 2);
        muR[fm * 2]     = mug[r];     nuR[fm * 2]     = nug[r];
        muR[fm * 2 + 1] = mug[r + 8]; nuR[fm * 2 + 1] = nug[r + 8];
    }
    #pragma unroll
    for (int fn = 0; fn < 4; fn++) {
        int c = col0 + wn + fn * 8 + (lane & 3) * 2;
        muC[fn * 2]     = mug[c];     nuC[fn * 2]     = nug[c];
        muC[fn * 2 + 1] = mug[c + 1]; nuC[fn * 2 + 1] = nug[c + 1];
    }

    #pragma unroll
    for (int fm = 0; fm < 4; fm++) {
        #pragma unroll
        for (int fn = 0; fn < 4; fn++) {
            #pragma unroll
            for (int q = 0; q < 4; q++) {
                int rr = fm * 2 + (q >> 1);
                int cc = fn * 2 + (q & 1);
                int rI = row0 + wm + fm * 16 + (lane >> 2) + (q >> 1) * 8;
                int cJ = col0 + wn + fn * 8 + (lane & 3) * 2 + (q & 1);
                float v = acc[fm][fn][q] * invM - muR[rr] * muC[cc] - nuR[rr] * nuC[cc];
                if (rI == cJ) v += 1e-8f;
                outb[(size_t)rI * NC + cJ] = v;
                outb[(size_t)cJ * NC + rI] = v;
            }
        }
    }
}

// ---------------------------------------------------------------------------
extern "C" void kernel_launch(void* const* d_in, const int* in_sizes, int n_in,
                              void* d_out, int out_size) {
    const float* h    = (const float*)d_in[0];
    const float* w    = (const float*)d_in[1];
    const float* bias = (const float*)d_in[2];
    float* out = (float*)d_out;

    static int init = 0;
    if (!init) {
        cudaFuncSetAttribute(syrk_hmma2, cudaFuncAttributeMaxDynamicSharedMemorySize,
                             SMEM_TOTAL);
        init = 1;
    }

    pe_kernel<<<NC, 256>>>();
    stats_kernel<<<(NB * NC) / 8, 256>>>(h);
    gate_kernel<<<(NB * NC + 255) / 256, 256>>>(w, bias);
    prep_kernel<<<NB * NC, 256>>>(h);
    dim3 grid(10, NB);
    syrk_hmma2<<<grid, 256, SMEM_TOTAL>>>(out);
}

// round 6
// speedup vs baseline: 2.7153x; 1.0032x over previous
#include <cuda_runtime.h>
#include <cuda_bf16.h>
#include <math.h>
#include <stdint.h>

#define NB 64
#define NC 512
#define NM 1024
#define NKW 5
#define LDT 40              // padded bf16 tile row stride (elements) -> 80B rows
#define TILE_BYTES (128 * LDT * 2)      // 10240
#define STAGE_BYTES (4 * TILE_BYTES)    // 40960
#define SMEM_TOTAL (2 * STAGE_BYTES)    // 81920

// Scratch
__device__ float g_pe[NC * NM];
__device__ float g_y[NB * NC];
__device__ float g_nu[NB * NC];
__device__ float g_gate[NB * NC];
__device__ float g_mu[NB * NC];
// bf16 hi/lo planes (64MB each)
__device__ __align__(16) __nv_bfloat16 g_hs_hi[NB * NC * NM];
__device__ __align__(16) __nv_bfloat16 g_hs_lo[NB * NC * NM];
__device__ __align__(16) __nv_bfloat16 g_hb_hi[NB * NC * NM];
__device__ __align__(16) __nv_bfloat16 g_hb_lo[NB * NC * NM];

__constant__ int2 c_tp[10] = {{0,0},{0,1},{0,2},{0,3},{1,1},{1,2},{1,3},{2,2},{2,3},{3,3}};

// ---------------------------------------------------------------------------
__global__ void pe_kernel() {
    int c = blockIdx.x;
    int i = c >> 1;
    float dv = expf(-(float)(2 * i) * (logf(10000.0f) / (float)NC));
    bool is_sin = (c & 1) == 0;
    for (int m = threadIdx.x; m < NM; m += blockDim.x) {
        float ang = (float)m * dv;
        g_pe[c * NM + m] = is_sin ? sinf(ang) : cosf(ang);
    }
}

__global__ void stats_kernel(const float* __restrict__ h) {
    int warp = (blockIdx.x * blockDim.x + threadIdx.x) >> 5;
    int lane = threadIdx.x & 31;
    if (warp >= NB * NC) return;
    int c = warp % NC;
    const float4* h4 = (const float4*)(h + (size_t)warp * NM);
    const float4* p4 = (const float4*)(g_pe + (size_t)c * NM);
    float sh = 0.f, sp = 0.f;
    for (int i = lane; i < NM / 4; i += 32) {
        float4 hv = h4[i];
        float4 pv = p4[i];
        sh += (hv.x + hv.y) + (hv.z + hv.w);
        sp += (pv.x + pv.y) + (pv.z + pv.w);
    }
    float sx = sh + sp;
    #pragma unroll
    for (int o = 16; o; o >>= 1) {
        sx += __shfl_xor_sync(0xffffffffu, sx, o);
        sh += __shfl_xor_sync(0xffffffffu, sh, o);
    }
    if (lane == 0) {
        g_y[warp]  = sx * (1.0f / NM);
        g_nu[warp] = sh * (1.0f / NM);
    }
}

__global__ void gate_kernel(const float* __restrict__ w, const float* __restrict__ bias) {
    int idx = blockIdx.x * blockDim.x + threadIdx.x;
    if (idx >= NB * NC) return;
    int b = idx / NC, c = idx % NC;
    float acc = bias[c];
    #pragma unroll
    for (int k = 0; k < NKW; k++) {
        int cc = c + k - 2;
        float yv = (cc >= 0 && cc < NC) ? g_y[b * NC + cc] : 0.0f;
        acc = fmaf(yv, w[c * NKW + k], acc);
    }
    float gate = 1.0f / (1.0f + expf(-acc));
    g_gate[idx] = gate;
    g_mu[idx]   = gate * g_y[idx];
}

// ---------------------------------------------------------------------------
__device__ __forceinline__ uint32_t pack2(__nv_bfloat16 a, __nv_bfloat16 b) {
    return (uint32_t)__bfloat16_as_ushort(a) | ((uint32_t)__bfloat16_as_ushort(b) << 16);
}
__device__ __forceinline__ void split4(float v0, float v1, float v2, float v3,
                                       uint2* hi, uint2* lo) {
    __nv_bfloat16 h0 = __float2bfloat16(v0), h1 = __float2bfloat16(v1);
    __nv_bfloat16 h2 = __float2bfloat16(v2), h3 = __float2bfloat16(v3);
    __nv_bfloat16 l0 = __float2bfloat16(v0 - __bfloat162float(h0));
    __nv_bfloat16 l1 = __float2bfloat16(v1 - __bfloat162float(h1));
    __nv_bfloat16 l2 = __float2bfloat16(v2 - __bfloat162float(h2));
    __nv_bfloat16 l3 = __float2bfloat16(v3 - __bfloat162float(h3));
    *hi = make_uint2(pack2(h0, h1), pack2(h2, h3));
    *lo = make_uint2(pack2(l0, l1), pack2(l2, l3));
}

__global__ __launch_bounds__(256) void prep_kernel(const float* __restrict__ h) {
    int rowid = blockIdx.x;              // b*NC + c
    int c = rowid & (NC - 1);
    int t = threadIdx.x;                 // one float4 per thread
    size_t e = (size_t)rowid * NM + t * 4;
    float4 hv = *(const float4*)(h + e);
    float4 pv = *(const float4*)(g_pe + (size_t)c * NM + t * 4);
    float gg = g_gate[rowid];
    uint2 hi, lo;
    split4((hv.x + pv.x) * gg, (hv.y + pv.y) * gg,
           (hv.z + pv.z) * gg, (hv.w + pv.w) * gg, &hi, &lo);
    *(uint2*)(g_hs_hi + e) = hi;
    *(uint2*)(g_hs_lo + e) = lo;
    split4(hv.x, hv.y, hv.z, hv.w, &hi, &lo);
    *(uint2*)(g_hb_hi + e) = hi;
    *(uint2*)(g_hb_lo + e) = lo;
}

// ---------------------------------------------------------------------------
__device__ __forceinline__ uint32_t smem_u32(const void* p) {
    uint32_t a;
    asm("{ .reg .u64 t; cvta.to.shared.u64 t, %1; cvt.u32.u64 %0, t; }" : "=r"(a) : "l"(p));
    return a;
}
__device__ __forceinline__ void ldsm_x4(uint32_t* r, uint32_t addr) {
    asm volatile("ldmatrix.sync.aligned.m8n8.x4.shared.b16 {%0,%1,%2,%3}, [%4];"
                 : "=r"(r[0]), "=r"(r[1]), "=r"(r[2]), "=r"(r[3]) : "r"(addr));
}
__device__ __forceinline__ void mma16816(float* d, const uint32_t* a, const uint32_t* b) {
    asm volatile(
        "mma.sync.aligned.m16n8k16.row.col.f32.bf16.bf16.f32 "
        "{%0,%1,%2,%3}, {%4,%5,%6,%7}, {%8,%9}, {%0,%1,%2,%3};"
        : "+f"(d[0]), "+f"(d[1]), "+f"(d[2]), "+f"(d[3])
        : "r"(a[0]), "r"(a[1]), "r"(a[2]), "r"(a[3]), "r"(b[0]), "r"(b[1]));
}
__device__ __forceinline__ void cp16(uint32_t dst, const void* src) {
    asm volatile("cp.async.cg.shared.global [%0], [%1], 16;" :: "r"(dst), "l"(src) : "memory");
}
__device__ __forceinline__ void cp_commit() {
    asm volatile("cp.async.commit_group;" ::: "memory");
}
template <int N>
__device__ __forceinline__ void cp_wait() {
    asm volatile("cp.async.wait_group %0;" :: "n"(N) : "memory");
}

extern __shared__ char dsm[];

__global__ __launch_bounds__(256, 2) void syrk_hmma2(float* __restrict__ out) {
    int tid = threadIdx.x;
    int lane = tid & 31;
    int wid = tid >> 5;
    int b = blockIdx.y;
    int2 tp = c_tp[blockIdx.x];
    int row0 = tp.x * 128;
    int col0 = tp.y * 128;

    uint32_t sb = smem_u32(dsm);

    // warp tile: 64 x 32
    int wm = (wid >> 2) * 64;
    int wn = (wid & 3) * 32;

    float acc[4][4][4];
    #pragma unroll
    for (int i = 0; i < 4; i++)
        #pragma unroll
        for (int j = 0; j < 4; j++)
            #pragma unroll
            for (int q = 0; q < 4; q++) acc[i][j][q] = 0.0f;

    // ldmatrix lane offsets (element units)
    int aRowOff = lane & 15;
    int aColOff = (lane >> 4) * 8;
    int bRowOff = (lane & 7) + ((lane >> 4) << 3);
    int bColOff = ((lane >> 3) & 1) * 8;

    const size_t rowbase = (size_t)b * NC;

    auto issue = [&](int s) {
        int part = s >> 5;               // 0 = hs, 1 = hb
        int k0 = (s & 31) * 32;
        uint32_t dstbase = sb + (uint32_t)(s & 1) * STAGE_BYTES;
        #pragma unroll
        for (int it = 0; it < 8; it++) {
            int item = it * 256 + tid;
            int t  = item >> 9;          // 0:A_hi 1:A_lo 2:B_hi 3:B_lo
            int r  = (item >> 2) & 127;
            int ch = item & 3;
            int row = ((t >= 2) ? col0 : row0) + r;
            const __nv_bfloat16* plane =
                part ? ((t & 1) ? g_hb_lo : g_hb_hi)
                     : ((t & 1) ? g_hs_lo : g_hs_hi);
            const void* src = plane + (rowbase + row) * NM + k0 + ch * 8;
            uint32_t dst = dstbase + (uint32_t)(t * TILE_BYTES + r * 80 + ch * 16);
            cp16(dst, src);
        }
        cp_commit();
    };

    issue(0);
    for (int s = 0; s < 64; s++) {
        if (s + 1 < 64) { issue(s + 1); cp_wait<1>(); }
        else            { cp_wait<0>(); }
        __syncthreads();

        uint32_t base = sb + (uint32_t)(s & 1) * STAGE_BYTES;
        uint32_t uAH = base;
        uint32_t uAL = base + TILE_BYTES;
        uint32_t uBH = base + 2 * TILE_BYTES;
        uint32_t uBL = base + 3 * TILE_BYTES;

        #pragma unroll
        for (int ks = 0; ks < 2; ks++) {
            int k0 = ks * 16;
            uint32_t aAddrBase = (uint32_t)((k0 + aColOff) * 2);
            uint32_t bAddrBase = (uint32_t)((k0 + bColOff) * 2);

            // --- B fragments (hi and lo), loaded once ---
            uint32_t bh[4][2], bl[4][2];
            #pragma unroll
            for (int half = 0; half < 2; half++) {
                uint32_t roff = (uint32_t)((wn + half * 16 + bRowOff) * LDT * 2);
                uint32_t r4[4];
                ldsm_x4(r4, uBH + roff + bAddrBase);
                bh[half * 2 + 0][0] = r4[0]; bh[half * 2 + 0][1] = r4[1];
                bh[half * 2 + 1][0] = r4[2]; bh[half * 2 + 1][1] = r4[3];
                ldsm_x4(r4, uBL + roff + bAddrBase);
                bl[half * 2 + 0][0] = r4[0]; bl[half * 2 + 0][1] = r4[1];
                bl[half * 2 + 1][0] = r4[2]; bl[half * 2 + 1][1] = r4[3];
            }

            // --- A_hi: HH + HL sections ---
            uint32_t af[4][4];
            #pragma unroll
            for (int fm = 0; fm < 4; fm++) {
                uint32_t addr = uAH +
                    (uint32_t)((wm + fm * 16 + aRowOff) * LDT * 2) + aAddrBase;
                ldsm_x4(af[fm], addr);
            }
            #pragma unroll
            for (int fm = 0; fm < 4; fm++)
                #pragma unroll
                for (int fn = 0; fn < 4; fn++)
                    mma16816(acc[fm][fn], af[fm], bh[fn]);
            #pragma unroll
            for (int fm = 0; fm < 4; fm++)
                #pragma unroll
                for (int fn = 0; fn < 4; fn++)
                    mma16816(acc[fm][fn], af[fm], bl[fn]);

            // --- A_lo: LH section (reuse af registers) ---
            #pragma unroll
            for (int fm = 0; fm < 4; fm++) {
                uint32_t addr = uAL +
                    (uint32_t)((wm + fm * 16 + aRowOff) * LDT * 2) + aAddrBase;
                ldsm_x4(af[fm], addr);
            }
            #pragma unroll
            for (int fm = 0; fm < 4; fm++)
                #pragma unroll
                for (int fn = 0; fn < 4; fn++)
                    mma16816(acc[fm][fn], af[fm], bh[fn]);
        }
        __syncthreads();
    }

    // ---- epilogue ----
    const float* mug = g_mu + b * NC;
    const float* nug = g_nu + b * NC;
    float* outb = out + (size_t)b * NC * NC;
    const float invM = 1.0f / (float)NM;

    float muR[8], nuR[8], muC[8], nuC[8];
    #pragma unroll
    for (int fm = 0; fm < 4; fm++) {
        int r = row0 + wm + fm * 16 + (lane >> 2);
        muR[fm * 2]     = mug[r];     nuR[fm * 2]     = nug[r];
        muR[fm * 2 + 1] = mug[r + 8]; nuR[fm * 2 + 1] = nug[r + 8];
    }
    #pragma unroll
    for (int fn = 0; fn < 4; fn++) {
        int c = col0 + wn + fn * 8 + (lane & 3) * 2;
        muC[fn * 2]     = mug[c];     nuC[fn * 2]     = nug[c];
        muC[fn * 2 + 1] = mug[c + 1]; nuC[fn * 2 + 1] = nug[c + 1];
    }

    #pragma unroll
    for (int fm = 0; fm < 4; fm++) {
        #pragma unroll
        for (int fn = 0; fn < 4; fn++) {
            #pragma unroll
            for (int q = 0; q < 4; q++) {
                int rr = fm * 2 + (q >> 1);
                int cc = fn * 2 + (q & 1);
                int rI = row0 + wm + fm * 16 + (lane >> 2) + (q >> 1) * 8;
                int cJ = col0 + wn + fn * 8 + (lane & 3) * 2 + (q & 1);
                float v = acc[fm][fn][q] * invM - muR[rr] * muC[cc] - nuR[rr] * nuC[cc];
                if (rI == cJ) v += 1e-8f;
                outb[(size_t)rI * NC + cJ] = v;
                outb[(size_t)cJ * NC + rI] = v;
            }
        }
    }
}

// ---------------------------------------------------------------------------
extern "C" void kernel_launch(void* const* d_in, const int* in_sizes, int n_in,
                              void* d_out, int out_size) {
    const float* h    = (const float*)d_in[0];
    const float* w    = (const float*)d_in[1];
    const float* bias = (const float*)d_in[2];
    float* out = (float*)d_out;

    static int init = 0;
    if (!init) {
        cudaFuncSetAttribute(syrk_hmma2, cudaFuncAttributeMaxDynamicSharedMemorySize,
                             SMEM_TOTAL);
        init = 1;
    }

    pe_kernel<<<NC, 256>>>();
    stats_kernel<<<(NB * NC) / 8, 256>>>(h);
    gate_kernel<<<(NB * NC + 255) / 256, 256>>>(w, bias);
    prep_kernel<<<NB * NC, 256>>>(h);
    dim3 grid(10, NB);
    syrk_hmma2<<<grid, 256, SMEM_TOTAL>>>(out);
}

// round 7
// speedup vs baseline: 3.8066x; 1.4019x over previous
#include <cuda_runtime.h>
#include <cuda_fp16.h>
#include <math.h>
#include <stdint.h>

#define NB 64
#define NC 512
#define NM 1024
#define NKW 5
#define LDT 40                           // padded fp16 row stride (elems) -> 80B
#define TILE_BYTES (128 * LDT * 2)       // 10240
#define STAGE_BYTES (3 * TILE_BYTES)     // 30720  (A_hi, B_hi, B_lo)
#define SMEM_TOTAL (2 * STAGE_BYTES)     // 61440

// Scratch
__device__ float g_pe[NC * NM];
__device__ float g_y[NB * NC];
__device__ float g_nu[NB * NC];
__device__ float g_gate[NB * NC];
__device__ float g_mu[NB * NC];
// fp16 hi/lo planes (64MB each)
__device__ __align__(16) __half g_hs_hi[NB * NC * NM];
__device__ __align__(16) __half g_hs_lo[NB * NC * NM];
__device__ __align__(16) __half g_hb_hi[NB * NC * NM];
__device__ __align__(16) __half g_hb_lo[NB * NC * NM];

__constant__ int2 c_tp[10] = {{0,0},{0,1},{0,2},{0,3},{1,1},{1,2},{1,3},{2,2},{2,3},{3,3}};

// ---------------------------------------------------------------------------
__global__ void pe_kernel() {
    int c = blockIdx.x;
    int i = c >> 1;
    float dv = expf(-(float)(2 * i) * (logf(10000.0f) / (float)NC));
    bool is_sin = (c & 1) == 0;
    for (int m = threadIdx.x; m < NM; m += blockDim.x) {
        float ang = (float)m * dv;
        g_pe[c * NM + m] = is_sin ? sinf(ang) : cosf(ang);
    }
}

__global__ void stats_kernel(const float* __restrict__ h) {
    int warp = (blockIdx.x * blockDim.x + threadIdx.x) >> 5;
    int lane = threadIdx.x & 31;
    if (warp >= NB * NC) return;
    int c = warp % NC;
    const float4* h4 = (const float4*)(h + (size_t)warp * NM);
    const float4* p4 = (const float4*)(g_pe + (size_t)c * NM);
    float sh = 0.f, sp = 0.f;
    for (int i = lane; i < NM / 4; i += 32) {
        float4 hv = h4[i];
        float4 pv = p4[i];
        sh += (hv.x + hv.y) + (hv.z + hv.w);
        sp += (pv.x + pv.y) + (pv.z + pv.w);
    }
    float sx = sh + sp;
    #pragma unroll
    for (int o = 16; o; o >>= 1) {
        sx += __shfl_xor_sync(0xffffffffu, sx, o);
        sh += __shfl_xor_sync(0xffffffffu, sh, o);
    }
    if (lane == 0) {
        g_y[warp]  = sx * (1.0f / NM);
        g_nu[warp] = sh * (1.0f / NM);
    }
}

__global__ void gate_kernel(const float* __restrict__ w, const float* __restrict__ bias) {
    int idx = blockIdx.x * blockDim.x + threadIdx.x;
    if (idx >= NB * NC) return;
    int b = idx / NC, c = idx % NC;
    float acc = bias[c];
    #pragma unroll
    for (int k = 0; k < NKW; k++) {
        int cc = c + k - 2;
        float yv = (cc >= 0 && cc < NC) ? g_y[b * NC + cc] : 0.0f;
        acc = fmaf(yv, w[c * NKW + k], acc);
    }
    float gate = 1.0f / (1.0f + expf(-acc));
    g_gate[idx] = gate;
    g_mu[idx]   = gate * g_y[idx];
}

// ---------------------------------------------------------------------------
__device__ __forceinline__ uint32_t pack2h(__half a, __half b) {
    return (uint32_t)__half_as_ushort(a) | ((uint32_t)__half_as_ushort(b) << 16);
}
__device__ __forceinline__ void split4h(float v0, float v1, float v2, float v3,
                                        uint2* hi, uint2* lo) {
    __half h0 = __float2half_rn(v0), h1 = __float2half_rn(v1);
    __half h2 = __float2half_rn(v2), h3 = __float2half_rn(v3);
    __half l0 = __float2half_rn(v0 - __half2float(h0));
    __half l1 = __float2half_rn(v1 - __half2float(h1));
    __half l2 = __float2half_rn(v2 - __half2float(h2));
    __half l3 = __float2half_rn(v3 - __half2float(h3));
    *hi = make_uint2(pack2h(h0, h1), pack2h(h2, h3));
    *lo = make_uint2(pack2h(l0, l1), pack2h(l2, l3));
}

__global__ __launch_bounds__(256) void prep_kernel(const float* __restrict__ h) {
    int rowid = blockIdx.x;              // b*NC + c
    int c = rowid & (NC - 1);
    int t = threadIdx.x;                 // one float4 per thread
    size_t e = (size_t)rowid * NM + t * 4;
    float4 hv = *(const float4*)(h + e);
    float4 pv = *(const float4*)(g_pe + (size_t)c * NM + t * 4);
    float gg = g_gate[rowid];
    uint2 hi, lo;
    split4h((hv.x + pv.x) * gg, (hv.y + pv.y) * gg,
            (hv.z + pv.z) * gg, (hv.w + pv.w) * gg, &hi, &lo);
    *(uint2*)(g_hs_hi + e) = hi;
    *(uint2*)(g_hs_lo + e) = lo;
    split4h(hv.x, hv.y, hv.z, hv.w, &hi, &lo);
    *(uint2*)(g_hb_hi + e) = hi;
    *(uint2*)(g_hb_lo + e) = lo;
}

// ---------------------------------------------------------------------------
__device__ __forceinline__ uint32_t smem_u32(const void* p) {
    uint32_t a;
    asm("{ .reg .u64 t; cvta.to.shared.u64 t, %1; cvt.u32.u64 %0, t; }" : "=r"(a) : "l"(p));
    return a;
}
__device__ __forceinline__ void ldsm_x4(uint32_t* r, uint32_t addr) {
    asm volatile("ldmatrix.sync.aligned.m8n8.x4.shared.b16 {%0,%1,%2,%3}, [%4];"
                 : "=r"(r[0]), "=r"(r[1]), "=r"(r[2]), "=r"(r[3]) : "r"(addr));
}
__device__ __forceinline__ void mma16816(float* d, const uint32_t* a, const uint32_t* b) {
    asm volatile(
        "mma.sync.aligned.m16n8k16.row.col.f32.f16.f16.f32 "
        "{%0,%1,%2,%3}, {%4,%5,%6,%7}, {%8,%9}, {%0,%1,%2,%3};"
        : "+f"(d[0]), "+f"(d[1]), "+f"(d[2]), "+f"(d[3])
        : "r"(a[0]), "r"(a[1]), "r"(a[2]), "r"(a[3]), "r"(b[0]), "r"(b[1]));
}
__device__ __forceinline__ void cp16(uint32_t dst, const void* src) {
    asm volatile("cp.async.cg.shared.global [%0], [%1], 16;" :: "r"(dst), "l"(src) : "memory");
}
__device__ __forceinline__ void cp_commit() {
    asm volatile("cp.async.commit_group;" ::: "memory");
}
template <int N>
__device__ __forceinline__ void cp_wait() {
    asm volatile("cp.async.wait_group %0;" :: "n"(N) : "memory");
}

extern __shared__ char dsm[];

__global__ __launch_bounds__(256, 2) void syrk_hmma3(float* __restrict__ out) {
    int tid = threadIdx.x;
    int lane = tid & 31;
    int wid = tid >> 5;
    int b = blockIdx.y;
    int2 tp = c_tp[blockIdx.x];
    int row0 = tp.x * 128;
    int col0 = tp.y * 128;
    bool diag = (row0 == col0);

    uint32_t sb = smem_u32(dsm);

    // warp tile: 64 x 32
    int wm = (wid >> 2) * 64;
    int wn = (wid & 3) * 32;

    float acc[4][4][4];
    #pragma unroll
    for (int i = 0; i < 4; i++)
        #pragma unroll
        for (int j = 0; j < 4; j++)
            #pragma unroll
            for (int q = 0; q < 4; q++) acc[i][j][q] = 0.0f;

    // ldmatrix lane offsets (element units)
    int aRowOff = lane & 15;
    int aColOff = (lane >> 4) * 8;
    int bRowOff = (lane & 7) + ((lane >> 4) << 3);
    int bColOff = ((lane >> 3) & 1) * 8;

    const size_t rowbase = (size_t)b * NC;

    // per-stage cp.async: 3 tiles (A_hi, B_hi, B_lo), 512 cp16/tile, 6/thread
    auto issue = [&](int s) {
        int part = s >> 5;               // 0 = hs, 1 = hb
        int k0 = (s & 31) * 32;
        uint32_t dstbase = sb + (uint32_t)(s & 1) * STAGE_BYTES;
        #pragma unroll
        for (int it = 0; it < 6; it++) {
            int item = it * 256 + tid;
            int t  = item >> 9;          // 0:A_hi 1:B_hi 2:B_lo
            int r  = (item >> 2) & 127;
            int ch = item & 3;
            int row = (t ? col0 : row0) + r;
            const __half* plane =
                part ? ((t == 2) ? g_hb_lo : g_hb_hi)
                     : ((t == 2) ? g_hs_lo : g_hs_hi);
            const void* src = plane + (rowbase + row) * NM + k0 + ch * 8;
            uint32_t dst = dstbase + (uint32_t)(t * TILE_BYTES + r * 80 + ch * 16);
            cp16(dst, src);
        }
        cp_commit();
    };

    issue(0);
    for (int s = 0; s < 64; s++) {
        if (s + 1 < 64) { issue(s + 1); cp_wait<1>(); }
        else            { cp_wait<0>(); }
        __syncthreads();

        uint32_t base = sb + (uint32_t)(s & 1) * STAGE_BYTES;
        uint32_t uA  = base;
        uint32_t uBH = base + TILE_BYTES;
        uint32_t uBL = base + 2 * TILE_BYTES;

        #pragma unroll
        for (int ks = 0; ks < 2; ks++) {
            int k0 = ks * 16;
            uint32_t aAddrBase = (uint32_t)((k0 + aColOff) * 2);
            uint32_t bAddrBase = (uint32_t)((k0 + bColOff) * 2);

            // B fragments (hi and lo)
            uint32_t bh[4][2], bl[4][2];
            #pragma unroll
            for (int half = 0; half < 2; half++) {
                uint32_t roff = (uint32_t)((wn + half * 16 + bRowOff) * LDT * 2);
                uint32_t r4[4];
                ldsm_x4(r4, uBH + roff + bAddrBase);
                bh[half * 2 + 0][0] = r4[0]; bh[half * 2 + 0][1] = r4[1];
                bh[half * 2 + 1][0] = r4[2]; bh[half * 2 + 1][1] = r4[3];
                ldsm_x4(r4, uBL + roff + bAddrBase);
                bl[half * 2 + 0][0] = r4[0]; bl[half * 2 + 0][1] = r4[1];
                bl[half * 2 + 1][0] = r4[2]; bl[half * 2 + 1][1] = r4[3];
            }

            // A_hi fragments
            uint32_t af[4][4];
            #pragma unroll
            for (int fm = 0; fm < 4; fm++) {
                uint32_t addr = uA +
                    (uint32_t)((wm + fm * 16 + aRowOff) * LDT * 2) + aAddrBase;
                ldsm_x4(af[fm], addr);
            }

            // sections: H*H' and H*L'
            #pragma unroll
            for (int fm = 0; fm < 4; fm++)
                #pragma unroll
                for (int fn = 0; fn < 4; fn++)
                    mma16816(acc[fm][fn], af[fm], bh[fn]);
            #pragma unroll
            for (int fm = 0; fm < 4; fm++)
                #pragma unroll
                for (int fn = 0; fn < 4; fn++)
                    mma16816(acc[fm][fn], af[fm], bl[fn]);
        }
        __syncthreads();
    }

    // ---- epilogue ----
    const float* mug = g_mu + b * NC;
    const float* nug = g_nu + b * NC;
    float* outb = out + (size_t)b * NC * NC;
    const float invM = 1.0f / (float)NM;

    float muR[8], nuR[8], muC[8], nuC[8];
    #pragma unroll
    for (int fm = 0; fm < 4; fm++) {
        int r = row0 + wm + fm * 16 + (lane >> 2);
        muR[fm * 2]     = mug[r];     nuR[fm * 2]     = nug[r];
        muR[fm * 2 + 1] = mug[r + 8]; nuR[fm * 2 + 1] = nug[r + 8];
    }
    #pragma unroll
    for (int fn = 0; fn < 4; fn++) {
        int c = col0 + wn + fn * 8 + (lane & 3) * 2;
        muC[fn * 2]     = mug[c];     nuC[fn * 2]     = nug[c];
        muC[fn * 2 + 1] = mug[c + 1]; nuC[fn * 2 + 1] = nug[c + 1];
    }

    #pragma unroll
    for (int fm = 0; fm < 4; fm++) {
        #pragma unroll
        for (int fn = 0; fn < 4; fn++) {
            #pragma unroll
            for (int q = 0; q < 4; q++) {
                int rr = fm * 2 + (q >> 1);
                int cc = fn * 2 + (q & 1);
                int rI = row0 + wm + fm * 16 + (lane >> 2) + (q >> 1) * 8;
                int cJ = col0 + wn + fn * 8 + (lane & 3) * 2 + (q & 1);
                float v = acc[fm][fn][q] * invM - muR[rr] * muC[cc] - nuR[rr] * nuC[cc];
                if (rI == cJ) v += 1e-8f;
                // diagonal tiles: Q is not symmetric (2-term split); keep only
                // the rI<=cJ value, mirrored — deterministic and single-writer.
                if (!diag || rI <= cJ) {
                    outb[(size_t)rI * NC + cJ] = v;
                    outb[(size_t)cJ * NC + rI] = v;
                }
            }
        }
    }
}

// ---------------------------------------------------------------------------
extern "C" void kernel_launch(void* const* d_in, const int* in_sizes, int n_in,
                              void* d_out, int out_size) {
    const float* h    = (const float*)d_in[0];
    const float* w    = (const float*)d_in[1];
    const float* bias = (const float*)d_in[2];
    float* out = (float*)d_out;

    static int init = 0;
    if (!init) {
        cudaFuncSetAttribute(syrk_hmma3, cudaFuncAttributeMaxDynamicSharedMemorySize,
                             SMEM_TOTAL);
        init = 1;
    }

    pe_kernel<<<NC, 256>>>();
    stats_kernel<<<(NB * NC) / 8, 256>>>(h);
    gate_kernel<<<(NB * NC + 255) / 256, 256>>>(w, bias);
    prep_kernel<<<NB * NC, 256>>>(h);
    dim3 grid(10, NB);
    syrk_hmma3<<<grid, 256, SMEM_TOTAL>>>(out);
}